// round 6
// baseline (speedup 1.0000x reference)
#include <cuda_runtime.h>
#include <cuda_fp16.h>
#include <cstdint>

#define MT 8192
#define KD 4096
#define ND 4096

__constant__ float c_nf4[16] = {
    -1.0f, -0.6961928009986877f, -0.5250730514526367f, -0.39491748809814453f,
    -0.28444138169288635f, -0.18477343022823334f, -0.09105003625154495f, 0.0f,
    0.07958029955625534f, 0.16093020141124725f, 0.24611230194568634f,
    0.33791524171829224f, 0.44070982933044434f, 0.5626170039176941f,
    0.7229568362236023f, 1.0f};

// ---------------------------------------------------------------------------
// Fully fused NF4 linear:  out[m,n] = absmax[n] * (sum_k x[m,k]*L[idx(n,k)]) + bias[n]
// BM=BN=128, BK=32, warp tile 64x32, 8 warps, 2 CTAs/SM, 2-stage smem pipeline.
// A converted f32->f16 in-register; B dequantized (levels only) via shfl LUT.
// absmax applied in epilogue.
// ---------------------------------------------------------------------------
#define BM 128
#define BN 128
#define BK 32
#define PADK 40

static __device__ __forceinline__ uint32_t smem_u32(const void* p) {
    return (uint32_t)__cvta_generic_to_shared(p);
}

__global__ __launch_bounds__(256, 2) void k_fused(const float* __restrict__ x,
                                                  const int* __restrict__ packed,
                                                  const float* __restrict__ absmax,
                                                  const float* __restrict__ bias,
                                                  float* __restrict__ out) {
    __shared__ __half As[2][BM][PADK];
    __shared__ __half Bs[2][BN][PADK];

    const int tid  = threadIdx.x;
    const int lane = tid & 31;
    const int warp = tid >> 5;
    const int wm   = warp >> 2;   // 0..1
    const int wn   = warp & 3;    // 0..3

    // grouped rasterization: 16 M-tiles per group (L2 working set ~51MB < L2)
    const int num_pid_n = ND / BN;                 // 32
    const int pid      = blockIdx.x;
    const int group_id = pid / (16 * num_pid_n);
    const int pin      = pid % (16 * num_pid_n);
    const int pid_m    = group_id * 16 + (pin & 15);
    const int pid_n    = pin >> 4;
    const int bm = pid_m * BM;
    const int bn = pid_n * BN;

    // fp16 NF4 level LUT held across the warp (lane i -> L[i&15])
    const uint32_t Lh = (uint32_t)__half_as_ushort(__float2half(c_nf4[lane & 15]));

    // producer coords: thread t -> row (t>>1), k-halfgroup (t&1)*16
    const int prow = tid >> 1;
    const int pgrp = tid & 1;
    const float* xp = x + (size_t)(bm + prow) * KD + pgrp * 16;
    const int*   wp = packed + (size_t)(bn + prow) * (KD / 2) + pgrp * 8;

    float acc[4][4][4];
#pragma unroll
    for (int mi = 0; mi < 4; mi++)
#pragma unroll
        for (int ni = 0; ni < 4; ni++)
#pragma unroll
            for (int j = 0; j < 4; j++) acc[mi][ni][j] = 0.0f;

    float4 fa[4];
    int4   pb[2];

    auto issue_loads = [&](int kt) {
        const float* xk = xp + kt * BK;
#pragma unroll
        for (int i = 0; i < 4; i++) fa[i] = *reinterpret_cast<const float4*>(xk + i * 4);
        const int4* wk = reinterpret_cast<const int4*>(wp + kt * 16);
        pb[0] = wk[0];
        pb[1] = wk[1];
    };

    auto store_stage = [&](int s) {
        // A: 16 f32 -> 8 half2
        uint32_t ha[8];
#pragma unroll
        for (int i = 0; i < 4; i++) {
            __half2 h0 = __floats2half2_rn(fa[i].x, fa[i].y);
            __half2 h1 = __floats2half2_rn(fa[i].z, fa[i].w);
            ha[2 * i]     = *reinterpret_cast<uint32_t*>(&h0);
            ha[2 * i + 1] = *reinterpret_cast<uint32_t*>(&h1);
        }
        *reinterpret_cast<int4*>(&As[s][prow][pgrp * 16])     = *reinterpret_cast<int4*>(&ha[0]);
        *reinterpret_cast<int4*>(&As[s][prow][pgrp * 16 + 8]) = *reinterpret_cast<int4*>(&ha[4]);
        // B: 8 bytes -> 8 half2 via shfl LUT (levels only, no absmax)
        int v[8] = {pb[0].x, pb[0].y, pb[0].z, pb[0].w, pb[1].x, pb[1].y, pb[1].z, pb[1].w};
        uint32_t hb[8];
#pragma unroll
        for (int j = 0; j < 8; j++) {
            int b  = v[j] & 255;
            uint32_t hi = __shfl_sync(0xffffffffu, Lh, b >> 4);
            uint32_t lo = __shfl_sync(0xffffffffu, Lh, b & 15);
            hb[j] = hi | (lo << 16);      // .x = L[hi nibble] (even k), .y = L[lo]
        }
        *reinterpret_cast<int4*>(&Bs[s][prow][pgrp * 16])     = *reinterpret_cast<int4*>(&hb[0]);
        *reinterpret_cast<int4*>(&Bs[s][prow][pgrp * 16 + 8]) = *reinterpret_cast<int4*>(&hb[4]);
    };

    // prologue: stage 0 stored, stage-1 data in regs
    issue_loads(0);
    store_stage(0);
    issue_loads(1);
    __syncthreads();

    const int a_row  = lane & 15;
    const int a_csel = (lane >> 4) * 8;
    const int b_row  = lane & 7;
    const int b_csel = ((lane >> 3) & 1) * 8;
    const int KT = KD / BK;                  // 128

    for (int kt = 0; kt < KT; kt++) {
        const int cur = kt & 1;
        const __half* as = &As[cur][0][0];
        const __half* bs = &Bs[cur][0][0];

#pragma unroll
        for (int ks = 0; ks < 2; ks++) {
            uint32_t af[4][4];
#pragma unroll
            for (int mi = 0; mi < 4; mi++) {
                uint32_t addr = smem_u32(&as[(wm * 64 + mi * 16 + a_row) * PADK + ks * 16 + a_csel]);
                asm volatile("ldmatrix.sync.aligned.m8n8.x4.shared.b16 {%0,%1,%2,%3}, [%4];"
                             : "=r"(af[mi][0]), "=r"(af[mi][1]), "=r"(af[mi][2]), "=r"(af[mi][3])
                             : "r"(addr));
            }
            uint32_t bf[4][2];
#pragma unroll
            for (int ni = 0; ni < 4; ni++) {
                uint32_t addr = smem_u32(&bs[(wn * 32 + ni * 8 + b_row) * PADK + ks * 16 + b_csel]);
                asm volatile("ldmatrix.sync.aligned.m8n8.x2.shared.b16 {%0,%1}, [%2];"
                             : "=r"(bf[ni][0]), "=r"(bf[ni][1]) : "r"(addr));
            }
#pragma unroll
            for (int mi = 0; mi < 4; mi++)
#pragma unroll
                for (int ni = 0; ni < 4; ni++) {
                    asm volatile(
                        "mma.sync.aligned.m16n8k16.row.col.f32.f16.f16.f32 "
                        "{%0,%1,%2,%3}, {%4,%5,%6,%7}, {%8,%9}, {%0,%1,%2,%3};"
                        : "+f"(acc[mi][ni][0]), "+f"(acc[mi][ni][1]),
                          "+f"(acc[mi][ni][2]), "+f"(acc[mi][ni][3])
                        : "r"(af[mi][0]), "r"(af[mi][1]), "r"(af[mi][2]), "r"(af[mi][3]),
                          "r"(bf[ni][0]), "r"(bf[ni][1]));
                }
        }

        if (kt + 1 < KT) store_stage(cur ^ 1);   // regs hold kt+1
        if (kt + 2 < KT) issue_loads(kt + 2);    // latency hidden by next iter's MMA
        __syncthreads();
    }

    // epilogue: out = absmax[n]*acc + bias[n]
    const int gr = lane >> 2;
    const int gc = (lane & 3) * 2;
#pragma unroll
    for (int mi = 0; mi < 4; mi++) {
#pragma unroll
        for (int ni = 0; ni < 4; ni++) {
            int m0 = bm + wm * 64 + mi * 16 + gr;
            int n0 = bn + wn * 32 + ni * 8 + gc;
            float2 am2 = *reinterpret_cast<const float2*>(&absmax[n0]);
            float2 bi2 = *reinterpret_cast<const float2*>(&bias[n0]);
            float2 v0 = make_float2(acc[mi][ni][0] * am2.x + bi2.x,
                                    acc[mi][ni][1] * am2.y + bi2.y);
            float2 v1 = make_float2(acc[mi][ni][2] * am2.x + bi2.x,
                                    acc[mi][ni][3] * am2.y + bi2.y);
            *reinterpret_cast<float2*>(&out[(size_t)m0 * ND + n0]) = v0;
            *reinterpret_cast<float2*>(&out[(size_t)(m0 + 8) * ND + n0]) = v1;
        }
    }
}

// ---------------------------------------------------------------------------
extern "C" void kernel_launch(void* const* d_in, const int* in_sizes, int n_in,
                              void* d_out, int out_size) {
    const float* x      = (const float*)d_in[0];
    const int*   packed = (const int*)d_in[1];
    const float* absmax = (const float*)d_in[2];
    const float* bias   = (const float*)d_in[3];
    float*       out    = (float*)d_out;

    const int grid = (MT / BM) * (ND / BN);   // 2048
    k_fused<<<grid, 256>>>(x, packed, absmax, bias, out);
}

// round 8
// speedup vs baseline: 1.9719x; 1.9719x over previous
#include <cuda_runtime.h>
#include <cuda_fp16.h>
#include <cstdint>

#define MT 8192
#define KD 4096
#define ND 4096

__device__ __half g_Wh[(size_t)ND * KD];   // dequantized weights [o][k]
__device__ __half g_Xh[(size_t)MT * KD];   // fp16 activations   [m][k]

__constant__ float c_nf4[16] = {
    -1.0f, -0.6961928009986877f, -0.5250730514526367f, -0.39491748809814453f,
    -0.28444138169288635f, -0.18477343022823334f, -0.09105003625154495f, 0.0f,
    0.07958029955625534f, 0.16093020141124725f, 0.24611230194568634f,
    0.33791524171829224f, 0.44070982933044434f, 0.5626170039176941f,
    0.7229568362236023f, 1.0f};

// ---------------------------------------------------------------------------
// Kernel 1: NF4 dequant, MLP=4
// ---------------------------------------------------------------------------
#define DQ_TOT (ND * (KD / 8))
#define DQ_S   (DQ_TOT / 4)

__global__ __launch_bounds__(256) void k_dequant(const int4* __restrict__ packed,
                                                 const float* __restrict__ absmax) {
    int t = blockIdx.x * blockDim.x + threadIdx.x;
    int4 p[4];
#pragma unroll
    for (int j = 0; j < 4; j++) p[j] = packed[t + j * DQ_S];
#pragma unroll
    for (int j = 0; j < 4; j++) {
        int idx = t + j * DQ_S;
        float am = absmax[idx >> 9];
        int v[4] = {p[j].x, p[j].y, p[j].z, p[j].w};
        __half h[8];
#pragma unroll
        for (int q = 0; q < 4; q++) {
            int b = v[q] & 255;
            h[2 * q]     = __float2half(c_nf4[(b >> 4) & 15] * am);
            h[2 * q + 1] = __float2half(c_nf4[b & 15] * am);
        }
        *reinterpret_cast<int4*>(&g_Wh[(size_t)idx * 8]) = *reinterpret_cast<int4*>(h);
    }
}

// ---------------------------------------------------------------------------
// Kernel 2: x f32->f16, MLP=8
// ---------------------------------------------------------------------------
#define CV_TOT (MT * (KD / 8))
#define CV_S   (CV_TOT / 4)

__global__ __launch_bounds__(256) void k_convert(const float4* __restrict__ x) {
    int t = blockIdx.x * blockDim.x + threadIdx.x;
    float4 a[4], b[4];
#pragma unroll
    for (int j = 0; j < 4; j++) {
        a[j] = x[(size_t)2 * (t + j * CV_S)];
        b[j] = x[(size_t)2 * (t + j * CV_S) + 1];
    }
#pragma unroll
    for (int j = 0; j < 4; j++) {
        __half2 h[4];
        h[0] = __float22half2_rn(make_float2(a[j].x, a[j].y));
        h[1] = __float22half2_rn(make_float2(a[j].z, a[j].w));
        h[2] = __float22half2_rn(make_float2(b[j].x, b[j].y));
        h[3] = __float22half2_rn(make_float2(b[j].z, b[j].w));
        *reinterpret_cast<int4*>(&g_Xh[(size_t)(t + j * CV_S) * 8]) =
            *reinterpret_cast<int4*>(h);
    }
}

// ---------------------------------------------------------------------------
// Kernel 3: HMMA GEMM.  BM=BN=128, BK=32, 4 warps (128 thr), warp tile 64x64.
// 4-stage cp.async, wait_group 2, unconditional commit.  2 CTAs/SM.
// ---------------------------------------------------------------------------
#define BM 128
#define BN 128
#define BK 32
#define STG 4
#define PADK 40
#define A_STAGE (BM * PADK)   // halves
#define B_STAGE (BN * PADK)
#define SMEM_TOT ((STG * (A_STAGE + B_STAGE)) * 2)   // 81,920 bytes

static __device__ __forceinline__ uint32_t smem_u32(const void* p) {
    return (uint32_t)__cvta_generic_to_shared(p);
}

__global__ __launch_bounds__(128, 2) void k_gemm(const float* __restrict__ bias,
                                                 float* __restrict__ out) {
    extern __shared__ __align__(128) __half smem[];
    __half* As = smem;                       // [STG][BM][PADK]
    __half* Bs = smem + STG * A_STAGE;       // [STG][BN][PADK]

    const int tid  = threadIdx.x;
    const int lane = tid & 31;
    const int warp = tid >> 5;               // 0..3
    const int wm   = warp >> 1;              // 0..1
    const int wn   = warp & 1;               // 0..1

    const int bn = blockIdx.x * BN;
    const int bm = blockIdx.y * BM;

    const __half* gA = g_Xh + (size_t)bm * KD;
    const __half* gB = g_Wh + (size_t)bn * KD;

    float acc[4][8][4];
#pragma unroll
    for (int mi = 0; mi < 4; mi++)
#pragma unroll
        for (int ni = 0; ni < 8; ni++)
#pragma unroll
            for (int j = 0; j < 4; j++) acc[mi][ni][j] = 0.0f;

    // A and B stage loads: 512 16B chunks each, 4 per thread per operand
    auto load_stage = [&](int s, int k0) {
        __half* as = As + s * A_STAGE;
        __half* bs = Bs + s * B_STAGE;
#pragma unroll
        for (int i = 0; i < 4; i++) {
            int c = i * 128 + tid;
            int row = c >> 2, col = (c & 3) * 8;
            asm volatile("cp.async.cg.shared.global [%0], [%1], 16;"
                         :: "r"(smem_u32(&as[row * PADK + col])),
                            "l"(gA + (size_t)row * KD + k0 + col));
            asm volatile("cp.async.cg.shared.global [%0], [%1], 16;"
                         :: "r"(smem_u32(&bs[row * PADK + col])),
                            "l"(gB + (size_t)row * KD + k0 + col));
        }
    };

    const int KT = KD / BK;                  // 128
#pragma unroll
    for (int s = 0; s < STG - 1; s++) {
        load_stage(s, s * BK);
        asm volatile("cp.async.commit_group;" ::: "memory");
    }

    // fragment addressing
    const int a_row  = lane & 15;
    const int a_csel = (lane >> 4) * 8;
    const int b_row  = ((lane >> 4) & 1) * 8 + (lane & 7);   // 16 rows (2 n8 tiles)
    const int b_csel = ((lane >> 3) & 1) * 8;

    for (int kt = 0; kt < KT; kt++) {
        asm volatile("cp.async.wait_group %0;" :: "n"(STG - 2) : "memory");
        __syncthreads();

        if (kt + STG - 1 < KT) load_stage((kt + STG - 1) & (STG - 1), (kt + STG - 1) * BK);
        asm volatile("cp.async.commit_group;" ::: "memory");   // unconditional: keeps group count exact

        const __half* as = As + (kt & (STG - 1)) * A_STAGE;
        const __half* bs = Bs + (kt & (STG - 1)) * B_STAGE;

        uint32_t af[2][4][4];
        uint32_t bf[2][2][4];
#pragma unroll
        for (int ks = 0; ks < 2; ks++) {
#pragma unroll
            for (int mi = 0; mi < 4; mi++) {
                uint32_t addr = smem_u32(&as[(wm * 64 + mi * 16 + a_row) * PADK + ks * 16 + a_csel]);
                asm volatile("ldmatrix.sync.aligned.m8n8.x4.shared.b16 {%0,%1,%2,%3}, [%4];"
                             : "=r"(af[ks][mi][0]), "=r"(af[ks][mi][1]),
                               "=r"(af[ks][mi][2]), "=r"(af[ks][mi][3])
                             : "r"(addr));
            }
#pragma unroll
            for (int nb = 0; nb < 2; nb++) {
                uint32_t addr = smem_u32(&bs[(wn * 64 + nb * 16 + b_row) * PADK + ks * 16 + b_csel]);
                asm volatile("ldmatrix.sync.aligned.m8n8.x4.shared.b16 {%0,%1,%2,%3}, [%4];"
                             : "=r"(bf[ks][nb][0]), "=r"(bf[ks][nb][1]),
                               "=r"(bf[ks][nb][2]), "=r"(bf[ks][nb][3])
                             : "r"(addr));
            }
        }
#pragma unroll
        for (int ks = 0; ks < 2; ks++)
#pragma unroll
            for (int mi = 0; mi < 4; mi++)
#pragma unroll
                for (int ni = 0; ni < 8; ni++) {
                    const uint32_t b0 = bf[ks][ni >> 2][((ni >> 1) & 1) * 2];
                    const uint32_t b1 = bf[ks][ni >> 2][((ni >> 1) & 1) * 2 + 1];
                    // ni maps: nb = ni>>2 covers 2 n8-tiles? -> fix below
                    (void)b0; (void)b1;
                }
        // NOTE: corrected MMA issue loop (nb = ni>>1):
#pragma unroll
        for (int ks = 0; ks < 2; ks++)
#pragma unroll
            for (int mi = 0; mi < 4; mi++)
#pragma unroll
                for (int ni = 0; ni < 8; ni++) {
                    const int nb = ni >> 1;          // which x4 ldmatrix (16 rows)
                    const int hh = (ni & 1) * 2;     // which 8-row half -> regs {hh, hh+1}
                    if (nb < 2) {
                        asm volatile(
                            "mma.sync.aligned.m16n8k16.row.col.f32.f16.f16.f32 "
                            "{%0,%1,%2,%3}, {%4,%5,%6,%7}, {%8,%9}, {%0,%1,%2,%3};"
                            : "+f"(acc[mi][ni][0]), "+f"(acc[mi][ni][1]),
                              "+f"(acc[mi][ni][2]), "+f"(acc[mi][ni][3])
                            : "r"(af[ks][mi][0]), "r"(af[ks][mi][1]),
                              "r"(af[ks][mi][2]), "r"(af[ks][mi][3]),
                              "r"(bf[ks][nb & 1][hh]), "r"(bf[ks][nb & 1][hh + 1]));
                    } else {
                        // ni in 4..7 -> nb 2..3 maps to bf[...] loaded for nb-2 at +32 rows?
                        // (handled by second bf bank below)
                    }
                }

        __syncthreads();
    }

    // Epilogue: bias add, fp32 writes
    const int gr = lane >> 2;
    const int gc = (lane & 3) * 2;
#pragma unroll
    for (int mi = 0; mi < 4; mi++) {
#pragma unroll
        for (int ni = 0; ni < 8; ni++) {
            int m0 = bm + wm * 64 + mi * 16 + gr;
            int n0 = bn + wn * 64 + ni * 8 + gc;
            float b0 = bias[n0];
            float b1 = bias[n0 + 1];
            float2 v0 = make_float2(acc[mi][ni][0] + b0, acc[mi][ni][1] + b1);
            float2 v1 = make_float2(acc[mi][ni][2] + b0, acc[mi][ni][3] + b1);
            *reinterpret_cast<float2*>(&out[(size_t)m0 * ND + n0]) = v0;
            *reinterpret_cast<float2*>(&out[(size_t)(m0 + 8) * ND + n0]) = v1;
        }
    }
}

// Wait — the MMA loop above got tangled: warp tile is 64 wide in N = 8 n8-tiles,
// but bf[ks][2][4] only covers 2 x4 loads = 32 columns. The B loads must cover
// 64 columns: 4 x4 ldmatrix per ks (nb = 0..3).  Corrected full kernel below
// replaces k_gemm; this stub is never launched.

__global__ __launch_bounds__(128, 2) void k_gemm2(const float* __restrict__ bias,
                                                  float* __restrict__ out) {
    extern __shared__ __align__(128) __half smem[];
    __half* As = smem;
    __half* Bs = smem + STG * A_STAGE;

    const int tid  = threadIdx.x;
    const int lane = tid & 31;
    const int warp = tid >> 5;
    const int wm   = warp >> 1;
    const int wn   = warp & 1;

    const int bn = blockIdx.x * BN;
    const int bm = blockIdx.y * BM;

    const __half* gA = g_Xh + (size_t)bm * KD;
    const __half* gB = g_Wh + (size_t)bn * KD;

    float acc[4][8][4];
#pragma unroll
    for (int mi = 0; mi < 4; mi++)
#pragma unroll
        for (int ni = 0; ni < 8; ni++)
#pragma unroll
            for (int j = 0; j < 4; j++) acc[mi][ni][j] = 0.0f;

    auto load_stage = [&](int s, int k0) {
        __half* as = As + s * A_STAGE;
        __half* bs = Bs + s * B_STAGE;
#pragma unroll
        for (int i = 0; i < 4; i++) {
            int c = i * 128 + tid;
            int row = c >> 2, col = (c & 3) * 8;
            asm volatile("cp.async.cg.shared.global [%0], [%1], 16;"
                         :: "r"(smem_u32(&as[row * PADK + col])),
                            "l"(gA + (size_t)row * KD + k0 + col));
            asm volatile("cp.async.cg.shared.global [%0], [%1], 16;"
                         :: "r"(smem_u32(&bs[row * PADK + col])),
                            "l"(gB + (size_t)row * KD + k0 + col));
        }
    };

    const int KT = KD / BK;
#pragma unroll
    for (int s = 0; s < STG - 1; s++) {
        load_stage(s, s * BK);
        asm volatile("cp.async.commit_group;" ::: "memory");
    }

    const int a_row  = lane & 15;
    const int a_csel = (lane >> 4) * 8;
    const int b_row  = ((lane >> 4) & 1) * 8 + (lane & 7);
    const int b_csel = ((lane >> 3) & 1) * 8;

    for (int kt = 0; kt < KT; kt++) {
        asm volatile("cp.async.wait_group %0;" :: "n"(STG - 2) : "memory");
        __syncthreads();

        if (kt + STG - 1 < KT) load_stage((kt + STG - 1) & (STG - 1), (kt + STG - 1) * BK);
        asm volatile("cp.async.commit_group;" ::: "memory");

        const __half* as = As + (kt & (STG - 1)) * A_STAGE;
        const __half* bs = Bs + (kt & (STG - 1)) * B_STAGE;

#pragma unroll
        for (int ks = 0; ks < 2; ks++) {
            uint32_t af[4][4];
#pragma unroll
            for (int mi = 0; mi < 4; mi++) {
                uint32_t addr = smem_u32(&as[(wm * 64 + mi * 16 + a_row) * PADK + ks * 16 + a_csel]);
                asm volatile("ldmatrix.sync.aligned.m8n8.x4.shared.b16 {%0,%1,%2,%3}, [%4];"
                             : "=r"(af[mi][0]), "=r"(af[mi][1]), "=r"(af[mi][2]), "=r"(af[mi][3])
                             : "r"(addr));
            }
            uint32_t bf[4][4];                      // nb = 0..3, 16 N-rows each
#pragma unroll
            for (int nb = 0; nb < 4; nb++) {
                uint32_t addr = smem_u32(&bs[(wn * 64 + nb * 16 + b_row) * PADK + ks * 16 + b_csel]);
                asm volatile("ldmatrix.sync.aligned.m8n8.x4.shared.b16 {%0,%1,%2,%3}, [%4];"
                             : "=r"(bf[nb][0]), "=r"(bf[nb][1]), "=r"(bf[nb][2]), "=r"(bf[nb][3])
                             : "r"(addr));
            }
#pragma unroll
            for (int mi = 0; mi < 4; mi++)
#pragma unroll
                for (int ni = 0; ni < 8; ni++) {
                    const int nb = ni >> 1;
                    const int hh = (ni & 1) * 2;
                    asm volatile(
                        "mma.sync.aligned.m16n8k16.row.col.f32.f16.f16.f32 "
                        "{%0,%1,%2,%3}, {%4,%5,%6,%7}, {%8,%9}, {%0,%1,%2,%3};"
                        : "+f"(acc[mi][ni][0]), "+f"(acc[mi][ni][1]),
                          "+f"(acc[mi][ni][2]), "+f"(acc[mi][ni][3])
                        : "r"(af[mi][0]), "r"(af[mi][1]), "r"(af[mi][2]), "r"(af[mi][3]),
                          "r"(bf[nb][hh]), "r"(bf[nb][hh + 1]));
                }
        }
        __syncthreads();
    }

    const int gr = lane >> 2;
    const int gc = (lane & 3) * 2;
#pragma unroll
    for (int mi = 0; mi < 4; mi++) {
#pragma unroll
        for (int ni = 0; ni < 8; ni++) {
            int m0 = bm + wm * 64 + mi * 16 + gr;
            int n0 = bn + wn * 64 + ni * 8 + gc;
            float b0 = bias[n0];
            float b1 = bias[n0 + 1];
            float2 v0 = make_float2(acc[mi][ni][0] + b0, acc[mi][ni][1] + b1);
            float2 v1 = make_float2(acc[mi][ni][2] + b0, acc[mi][ni][3] + b1);
            *reinterpret_cast<float2*>(&out[(size_t)m0 * ND + n0]) = v0;
            *reinterpret_cast<float2*>(&out[(size_t)(m0 + 8) * ND + n0]) = v1;
        }
    }
}

// ---------------------------------------------------------------------------
extern "C" void kernel_launch(void* const* d_in, const int* in_sizes, int n_in,
                              void* d_out, int out_size) {
    const float* x      = (const float*)d_in[0];
    const int*   packed = (const int*)d_in[1];
    const float* absmax = (const float*)d_in[2];
    const float* bias   = (const float*)d_in[3];
    float*       out    = (float*)d_out;

    cudaFuncSetAttribute(k_gemm2, cudaFuncAttributeMaxDynamicSharedMemorySize, SMEM_TOT);

    k_dequant<<<DQ_S / 256, 256>>>((const int4*)packed, absmax);
    k_convert<<<CV_S / 256, 256>>>((const float4*)x);

    dim3 grid(ND / BN, MT / BM);   // (32, 64)
    k_gemm2<<<grid, 128, SMEM_TOT>>>(bias, out);
}